// round 1
// baseline (speedup 1.0000x reference)
#include <cuda_runtime.h>
#include <math.h>

// Problem constants (from reference): N=8 (7 completed blocks + partial),
// B=2, L=4096, D=2048. BL = B*L passed at runtime.
#define NB 8
#define DDIM 2048
#define THREADS 256

__global__ __launch_bounds__(THREADS, 2)
void attn_residual_kernel(const float* __restrict__ blocks,    // [7, BL, D]
                          const float* __restrict__ partial,   // [BL, D]
                          const float* __restrict__ norm_scale,// [D]
                          const float* __restrict__ proj,      // [D]
                          float* __restrict__ out,             // [BL, D]
                          int BL)
{
    const int row  = blockIdx.x;        // (b,l) flattened
    const int t    = threadIdx.x;
    const int lane = t & 31;
    const int warp = t >> 5;

    const size_t rowOff  = (size_t)row * DDIM;
    const size_t nStride = (size_t)BL * DDIM;

    // Each thread owns two float4 chunks: d0 in [0,1024), d1 in [1024,2048).
    const int d0 = t * 4;
    const int d1 = 1024 + t * 4;

    // q[d] = proj[d] * norm_scale[d]
    float4 q0, q1;
    {
        float4 p = *(const float4*)(proj + d0);
        float4 s = *(const float4*)(norm_scale + d0);
        q0 = make_float4(p.x * s.x, p.y * s.y, p.z * s.z, p.w * s.w);
        p = *(const float4*)(proj + d1);
        s = *(const float4*)(norm_scale + d1);
        q1 = make_float4(p.x * s.x, p.y * s.y, p.z * s.z, p.w * s.w);
    }

    // Load all 8 blocks' row slices into registers; accumulate per-n partials.
    float4 v0[NB], v1[NB];
    float dotp[NB], ssq[NB];

#pragma unroll
    for (int n = 0; n < NB; n++) {
        const float* src = (n < NB - 1) ? (blocks + (size_t)n * nStride + rowOff)
                                        : (partial + rowOff);
        float4 a = *(const float4*)(src + d0);
        float4 b = *(const float4*)(src + d1);
        v0[n] = a;
        v1[n] = b;
        dotp[n] = q0.x * a.x + q0.y * a.y + q0.z * a.z + q0.w * a.w
                + q1.x * b.x + q1.y * b.y + q1.z * b.z + q1.w * b.w;
        ssq[n]  = a.x * a.x + a.y * a.y + a.z * a.z + a.w * a.w
                + b.x * b.x + b.y * b.y + b.z * b.z + b.w * b.w;
    }

    // ---- Block reduction of 16 scalars (dotp[0..7], ssq[0..7]) ----
    __shared__ float red[THREADS / 32][16];
    __shared__ float fin[16];

#pragma unroll
    for (int n = 0; n < NB; n++) {
#pragma unroll
        for (int o = 16; o > 0; o >>= 1) {
            dotp[n] += __shfl_down_sync(0xffffffffu, dotp[n], o);
            ssq[n]  += __shfl_down_sync(0xffffffffu, ssq[n],  o);
        }
    }
    if (lane == 0) {
#pragma unroll
        for (int n = 0; n < NB; n++) {
            red[warp][n]     = dotp[n];
            red[warp][8 + n] = ssq[n];
        }
    }
    __syncthreads();
    if (t < 16) {
        float s = 0.f;
#pragma unroll
        for (int w = 0; w < THREADS / 32; w++) s += red[w][t];
        fin[t] = s;
    }
    __syncthreads();

    // ---- Softmax over n (redundant per-thread; 8 elems, trivial) ----
    float logit[NB];
    float mx = -INFINITY;
#pragma unroll
    for (int n = 0; n < NB; n++) {
        float rms = sqrtf(fin[8 + n] * (1.0f / DDIM) + 1e-6f);
        logit[n] = fin[n] / rms;
        mx = fmaxf(mx, logit[n]);
    }
    float wsum = 0.f;
#pragma unroll
    for (int n = 0; n < NB; n++) {
        logit[n] = __expf(logit[n] - mx);
        wsum += logit[n];
    }
    const float inv = 1.0f / wsum;

    // ---- Weighted sum from register-resident V; coalesced store ----
    float4 o0 = make_float4(0.f, 0.f, 0.f, 0.f);
    float4 o1 = make_float4(0.f, 0.f, 0.f, 0.f);
#pragma unroll
    for (int n = 0; n < NB; n++) {
        float w = logit[n] * inv;
        o0.x += w * v0[n].x; o0.y += w * v0[n].y;
        o0.z += w * v0[n].z; o0.w += w * v0[n].w;
        o1.x += w * v1[n].x; o1.y += w * v1[n].y;
        o1.z += w * v1[n].z; o1.w += w * v1[n].w;
    }
    *(float4*)(out + rowOff + d0) = o0;
    *(float4*)(out + rowOff + d1) = o1;
}

extern "C" void kernel_launch(void* const* d_in, const int* in_sizes, int n_in,
                              void* d_out, int out_size)
{
    const float* blocks     = (const float*)d_in[0]; // [7, B, L, D]
    const float* partial    = (const float*)d_in[1]; // [B, L, D]
    const float* norm_scale = (const float*)d_in[2]; // [D]
    const float* proj       = (const float*)d_in[3]; // [D]
    float* out              = (float*)d_out;         // [B, L, D]

    const int BL = in_sizes[1] / DDIM;               // B*L rows

    attn_residual_kernel<<<BL, THREADS>>>(blocks, partial, norm_scale, proj,
                                          out, BL);
}

// round 3
// speedup vs baseline: 1.0453x; 1.0453x over previous
#include <cuda_runtime.h>
#include <cstdint>
#include <math.h>

// N=8 (7 completed blocks + partial), D=2048, B*L=8192 rows.
#define NB 8
#define DDIM 2048
#define THREADS 256
#define SMEM_BYTES (NB * DDIM * 4)   // 64 KB row stage

__device__ __forceinline__ void cp_async16(unsigned int smem_addr, const void* gptr) {
    asm volatile("cp.async.cg.shared.global [%0], [%1], 16;\n"
                 :: "r"(smem_addr), "l"(gptr));
}

__global__ __launch_bounds__(THREADS, 3)
void attn_residual_kernel(const float* __restrict__ blocks,     // [7, BL, D]
                          const float* __restrict__ partial,    // [BL, D]
                          const float* __restrict__ norm_scale, // [D]
                          const float* __restrict__ proj,       // [D]
                          float* __restrict__ out,              // [BL, D]
                          int BL)
{
    extern __shared__ float sv[];        // [NB][DDIM]
    const int row  = blockIdx.x;
    const int t    = threadIdx.x;
    const int lane = t & 31;
    const int warp = t >> 5;

    const size_t rowOff  = (size_t)row * DDIM;
    const size_t nStride = (size_t)BL * DDIM;

    const int d0 = t * 4;            // [0, 1024)
    const int d1 = 1024 + t * 4;     // [1024, 2048)

    // ---- Stage all 8 row slices into smem via cp.async (no reg staging) ----
    unsigned int svb;
    asm("{ .reg .u64 tmp; cvta.to.shared.u64 tmp, %1; cvt.u32.u64 %0, tmp; }"
        : "=r"(svb) : "l"(sv));
#pragma unroll
    for (int n = 0; n < NB; n++) {
        const float* src = (n < NB - 1) ? (blocks + (size_t)n * nStride + rowOff)
                                        : (partial + rowOff);
        cp_async16(svb + (unsigned)(n * DDIM + d0) * 4u, src + d0);
        cp_async16(svb + (unsigned)(n * DDIM + d1) * 4u, src + d1);
    }
    asm volatile("cp.async.commit_group;\n" ::: "memory");

    // q[d] = proj[d] * norm_scale[d] (overlaps with cp.async)
    float4 q0, q1;
    {
        float4 p = *(const float4*)(proj + d0);
        float4 s = *(const float4*)(norm_scale + d0);
        q0 = make_float4(p.x * s.x, p.y * s.y, p.z * s.z, p.w * s.w);
        p = *(const float4*)(proj + d1);
        s = *(const float4*)(norm_scale + d1);
        q1 = make_float4(p.x * s.x, p.y * s.y, p.z * s.z, p.w * s.w);
    }

    asm volatile("cp.async.wait_group 0;\n" ::: "memory");

    // ---- Pass 1: dot & sumsq per n (each thread reads only its own data) ----
    float dotp[NB], ssq[NB];
#pragma unroll
    for (int n = 0; n < NB; n++) {
        float4 a = *(const float4*)(sv + n * DDIM + d0);
        float4 b = *(const float4*)(sv + n * DDIM + d1);
        dotp[n] = q0.x * a.x + q0.y * a.y + q0.z * a.z + q0.w * a.w
                + q1.x * b.x + q1.y * b.y + q1.z * b.z + q1.w * b.w;
        ssq[n]  = a.x * a.x + a.y * a.y + a.z * a.z + a.w * a.w
                + b.x * b.x + b.y * b.y + b.z * b.z + b.w * b.w;
    }

    // ---- Block reduction of 16 scalars ----
    __shared__ float red[THREADS / 32][16];
    __shared__ float fin[16];
#pragma unroll
    for (int n = 0; n < NB; n++) {
#pragma unroll
        for (int o = 16; o > 0; o >>= 1) {
            dotp[n] += __shfl_down_sync(0xffffffffu, dotp[n], o);
            ssq[n]  += __shfl_down_sync(0xffffffffu, ssq[n],  o);
        }
    }
    if (lane == 0) {
#pragma unroll
        for (int n = 0; n < NB; n++) {
            red[warp][n]     = dotp[n];
            red[warp][8 + n] = ssq[n];
        }
    }
    __syncthreads();
    if (t < 16) {
        float s = 0.f;
#pragma unroll
        for (int w = 0; w < THREADS / 32; w++) s += red[w][t];
        fin[t] = s;
    }
    __syncthreads();

    // ---- Softmax over n (redundant per-thread; trivial) ----
    float wgt[NB];
    float mx = -INFINITY;
#pragma unroll
    for (int n = 0; n < NB; n++) {
        float rms = sqrtf(fin[8 + n] * (1.0f / DDIM) + 1e-6f);
        wgt[n] = fin[n] / rms;
        mx = fmaxf(mx, wgt[n]);
    }
    float wsum = 0.f;
#pragma unroll
    for (int n = 0; n < NB; n++) {
        wgt[n] = __expf(wgt[n] - mx);
        wsum += wgt[n];
    }
    const float inv = 1.0f / wsum;

    // ---- Pass 2: weighted sum from smem; coalesced store ----
    float4 o0 = make_float4(0.f, 0.f, 0.f, 0.f);
    float4 o1 = make_float4(0.f, 0.f, 0.f, 0.f);
#pragma unroll
    for (int n = 0; n < NB; n++) {
        float w = wgt[n] * inv;
        float4 a = *(const float4*)(sv + n * DDIM + d0);
        float4 b = *(const float4*)(sv + n * DDIM + d1);
        o0.x += w * a.x; o0.y += w * a.y; o0.z += w * a.z; o0.w += w * a.w;
        o1.x += w * b.x; o1.y += w * b.y; o1.z += w * b.z; o1.w += w * b.w;
    }
    *(float4*)(out + rowOff + d0) = o0;
    *(float4*)(out + rowOff + d1) = o1;
}

extern "C" void kernel_launch(void* const* d_in, const int* in_sizes, int n_in,
                              void* d_out, int out_size)
{
    const float* blocks     = (const float*)d_in[0];
    const float* partial    = (const float*)d_in[1];
    const float* norm_scale = (const float*)d_in[2];
    const float* proj       = (const float*)d_in[3];
    float* out              = (float*)d_out;

    const int BL = in_sizes[1] / DDIM;

    static int configured = 0;
    if (!configured) {
        cudaFuncSetAttribute(attn_residual_kernel,
                             cudaFuncAttributeMaxDynamicSharedMemorySize,
                             SMEM_BYTES);
        configured = 1;
    }

    attn_residual_kernel<<<BL, THREADS, SMEM_BYTES>>>(blocks, partial,
                                                      norm_scale, proj,
                                                      out, BL);
}